// round 12
// baseline (speedup 1.0000x reference)
#include <cuda_runtime.h>
#include <cuda_bf16.h>

// ChamferLoss R12: register colmin WITHOUT unroll explosion.
// Lesson R2..R11: colmin in registers needs a fully-unrolled column loop;
// 16 unrolled iterations blow live ranges (248 regs, spills); SMEM colmin
// RMW is too expensive per iteration. Fix: warp owns only a 256-column
// quarter -> colmin[8] regs, column loop = 4 fully-unrolled iterations.
// Grid = 2 CTAs/pair (512 rows each), __launch_bounds__(256,2) -> 2 resident
// CTAs, 4 warps/SMSP. 8 warps = 2 row-halves x 4 col-quarters.
// Math unchanged: u = 0.5*d^2 via packed f32x2 FMA (norms folded into init);
// sqrt hoisted outside mins. Row mins: lo/hi chains -> shfl -> SMEM atomicMin
// (merges 4 col-quarter warps). Col mins: SMEM atomicMin (merges 2 row-half
// warps) -> global atomicMax on COMPLEMENTED bits across the 2 sibling CTAs
// (zero identity; consumer resets -> graph-replay safe). Pair ticket: 2nd CTA
// computes pair colsum; global ticket: last CTA does the fixed-order final
// reduction. Fully deterministic.

#define NPTS    1024
#define THREADS 256
#define NWARPS  8
#define RG      4
#define CB_MAX  128

typedef unsigned long long ull;

#define PACK2(d, lo, hi) \
    asm("mov.b64 %0, {%1,%2};" : "=l"(d) : "f"(lo), "f"(hi))
#define UNPACK2(lo, hi, s) \
    asm("mov.b64 {%0,%1}, %2;" : "=f"(lo), "=f"(hi) : "l"(s))
#define FMA2(d, a, b, c) \
    asm("fma.rn.f32x2 %0, %1, %2, %3;" : "=l"(d) : "l"(a), "l"(b), "l"(c))
#define ADD2(d, a, b) \
    asm("add.rn.f32x2 %0, %1, %2;" : "=l"(d) : "l"(a), "l"(b))

__device__ unsigned g_colmin[CB_MAX * NPTS];  // zero-init; key = ~bits(min 0.5d2)
__device__ float    g_rowpart[2 * CB_MAX];
__device__ float    g_pairsum[CB_MAX];
__device__ int      g_paircnt[CB_MAX];        // zero-init; reset by consumer
__device__ int      g_done;                   // zero-init; reset by last CTA

__global__ __launch_bounds__(THREADS, 2)
void chamfer_pair_kernel(const float* __restrict__ p, const float* __restrict__ q,
                         float* __restrict__ out, int cb_count) {
    __shared__ __align__(16) float qx_s[NPTS], qy_s[NPTS], qz_s[NPTS], qs_s[NPTS];
    __shared__ unsigned rowmin_sh[NPTS / 2];   // 512 local rows
    __shared__ unsigned colmin_sh[NPTS];
    __shared__ float sred[NWARPS];
    __shared__ int sh_flag;

    const int cta  = blockIdx.x;
    const int pair = cta >> 1;
    const int half = cta & 1;          // which 512-row half of p
    const int tid  = threadIdx.x;
    const int warp = tid >> 5;
    const int lane = tid & 31;
    const int rh = warp >> 2;          // row half 0..1  (256 local rows)
    const int cq = warp & 3;           // column quarter 0..3 (256 cols)
    const float INF = __int_as_float(0x7f800000);

    const float4* __restrict__ qp = reinterpret_cast<const float4*>(q) + (size_t)pair * NPTS;
    const float4* __restrict__ pp = reinterpret_cast<const float4*>(p) + (size_t)pair * NPTS
                                    + half * (NPTS / 2);

    // Stage q (SoA + half-norm); init min buffers.
    for (int i = tid; i < NPTS; i += THREADS) {
        float4 v = qp[i];
        qx_s[i] = v.y; qy_s[i] = v.z; qz_s[i] = v.w;
        qs_s[i] = 0.5f * (v.y * v.y + v.z * v.z + v.w * v.w);
        colmin_sh[i] = 0x7f800000u;
    }
    for (int i = tid; i < NPTS / 2; i += THREADS) rowmin_sh[i] = 0x7f800000u;
    __syncthreads();

    // Per-lane column mins for this warp's quarter: cols cq*256 + j2*64 + 2*lane+k.
    float colmin[8];
    #pragma unroll
    for (int j = 0; j < 8; ++j) colmin[j] = INF;

    const int colbase0 = cq << 8;

    #pragma unroll 1
    for (int rg = 0; rg < 64; ++rg) {              // 64 groups of 4 local rows
        const int row0 = rh * 256 + rg * RG;       // local row (0..511)
        ull pnx2[RG], pny2[RG], pnz2[RG], psq2[RG];
        float rl[RG], rhh[RG];
        #pragma unroll
        for (int r = 0; r < RG; ++r) {
            float4 u = pp[row0 + r];               // uniform addr -> broadcast
            float a = -u.y, b = -u.z, c = -u.w;
            float s = 0.5f * (u.y * u.y + u.z * u.z + u.w * u.w);
            PACK2(pnx2[r], a, a);
            PACK2(pny2[r], b, b);
            PACK2(pnz2[r], c, c);
            PACK2(psq2[r], s, s);
            rl[r] = INF; rhh[r] = INF;
        }
        #pragma unroll
        for (int j2 = 0; j2 < 4; ++j2) {           // 64 cols per j2; 256 total
            const int base = colbase0 + (j2 << 6) + (lane << 1);
            ull xx2 = *reinterpret_cast<const ull*>(qx_s + base);
            ull yy2 = *reinterpret_cast<const ull*>(qy_s + base);
            ull zz2 = *reinterpret_cast<const ull*>(qz_s + base);
            ull ss2 = *reinterpret_cast<const ull*>(qs_s + base);
            #pragma unroll
            for (int r = 0; r < RG; ++r) {
                ull acc;
                ADD2(acc, ss2, psq2[r]);           // 0.5|q|^2 + 0.5|p|^2 (2 cols)
                FMA2(acc, pnx2[r], xx2, acc);      // - px*qx
                FMA2(acc, pny2[r], yy2, acc);
                FMA2(acc, pnz2[r], zz2, acc);      // acc = 0.5*d2 (2 cols)
                float u0, u1;
                UNPACK2(u0, u1, acc);
                colmin[2 * j2]     = fminf(colmin[2 * j2],     u0);
                colmin[2 * j2 + 1] = fminf(colmin[2 * j2 + 1], u1);
                rl[r]  = fminf(rl[r],  u0);        // independent lo/hi chains
                rhh[r] = fminf(rhh[r], u1);
            }
        }
        // Row mins over this warp's 256 cols -> SMEM atomicMin (4 warps/row).
        #pragma unroll
        for (int r = 0; r < RG; ++r) {
            float m = fminf(rl[r], rhh[r]);
            #pragma unroll
            for (int off = 16; off > 0; off >>= 1)
                m = fminf(m, __shfl_xor_sync(0xffffffffu, m, off));
            if (lane == 0)
                atomicMin(&rowmin_sh[row0 + r], __float_as_uint(fmaxf(m, 0.0f)));
        }
    }

    // Column-min merge within CTA (2 row-half warps share each quarter).
    #pragma unroll
    for (int j2 = 0; j2 < 4; ++j2) {
        #pragma unroll
        for (int k = 0; k < 2; ++k) {
            int c = colbase0 + (j2 << 6) + (lane << 1) + k;
            float v = fmaxf(colmin[2 * j2 + k], 0.0f);
            atomicMin(&colmin_sh[c], __float_as_uint(v));
        }
    }
    __syncthreads();

    // Row-distance partial for this CTA (512 rows, fixed order).
    float acc = 0.0f;
    for (int i = tid; i < NPTS / 2; i += THREADS)
        acc += sqrtf(2.0f * __uint_as_float(rowmin_sh[i]) + 1e-12f);  // clamped
    #pragma unroll
    for (int off = 16; off > 0; off >>= 1)
        acc += __shfl_xor_sync(0xffffffffu, acc, off);
    if (lane == 0) sred[warp] = acc;

    // Push CTA column mins to global (merge across the 2 sibling CTAs).
    for (int c = tid; c < NPTS; c += THREADS) {
        unsigned key = ~colmin_sh[c];              // values already clamped
        atomicMax(&g_colmin[pair * NPTS + c], key);
    }
    __syncthreads();

    if (tid == 0) {
        float s = 0.0f;
        #pragma unroll
        for (int w = 0; w < NWARPS; ++w) s += sred[w];
        g_rowpart[cta] = s;
        __threadfence();                  // order colmin/rowpart before ticket
        int prev = atomicAdd(&g_paircnt[pair], 1);
        sh_flag = (prev == 1) ? 1 : 0;    // 2 CTAs per pair
    }
    __syncthreads();

    // Second CTA of the pair: column sum for the pair (all mins in L2).
    if (sh_flag) {
        __threadfence();
        const uint4* src = reinterpret_cast<const uint4*>(g_colmin) + pair * (NPTS / 4) + tid;
        uint4 k = __ldcg(src);            // bypass L1 -> see both CTAs' atomics
        uint4* dst = reinterpret_cast<uint4*>(g_colmin) + pair * (NPTS / 4) + tid;
        *dst = make_uint4(0u, 0u, 0u, 0u);   // reset for next graph replay
        float s = sqrtf(2.0f * __uint_as_float(~k.x) + 1e-12f)
                + sqrtf(2.0f * __uint_as_float(~k.y) + 1e-12f)
                + sqrtf(2.0f * __uint_as_float(~k.z) + 1e-12f)
                + sqrtf(2.0f * __uint_as_float(~k.w) + 1e-12f);
        #pragma unroll
        for (int off = 16; off > 0; off >>= 1)
            s += __shfl_xor_sync(0xffffffffu, s, off);
        if (lane == 0) sred[warp] = s;
        __syncthreads();
        if (tid == 0) {
            float b = 0.0f;
            #pragma unroll
            for (int w = 0; w < NWARPS; ++w) b += sred[w];
            g_pairsum[pair] = b;
            g_paircnt[pair] = 0;          // reset ticket for next replay
        }
    }

    // Global done-ticket; last CTA does the deterministic final reduction.
    __syncthreads();
    if (tid == 0) {
        __threadfence();
        int prev = atomicAdd(&g_done, 1);
        sh_flag = (prev == 2 * cb_count - 1) ? 1 : 0;
    }
    __syncthreads();
    if (sh_flag) {
        __threadfence();
        float v = 0.0f;
        if (tid < cb_count)     v += __ldcg(&g_pairsum[tid]);
        if (tid < 2 * cb_count) v += __ldcg(&g_rowpart[tid]);
        #pragma unroll
        for (int off = 16; off > 0; off >>= 1)
            v += __shfl_xor_sync(0xffffffffu, v, off);
        if (lane == 0) sred[warp] = v;
        __syncthreads();
        if (tid == 0) {
            float tot = 0.0f;
            #pragma unroll
            for (int w = 0; w < NWARPS; ++w) tot += sred[w];
            out[0] = tot;
            g_done = 0;                   // reset for next graph replay
        }
    }
}

extern "C" void kernel_launch(void* const* d_in, const int* in_sizes, int n_in,
                              void* d_out, int out_size) {
    const float* p = (const float*)d_in[0];
    const float* q = (const float*)d_in[1];
    float* out = (float*)d_out;

    int cb = in_sizes[0] / (NPTS * 4);   // = 128 for (2,64,1024,4)
    if (cb > CB_MAX) cb = CB_MAX;

    chamfer_pair_kernel<<<2 * cb, THREADS>>>(p, q, out, cb);
}

// round 14
// speedup vs baseline: 1.2515x; 1.2515x over previous
#include <cuda_runtime.h>
#include <cuda_bf16.h>

// ChamferLoss R13: R7 loop shape (the fastest measured) with the two register
// blocks that caused R7's spills cut in half:
//  - warps split columns in half -> colmin[16] regs (was 32), column loop is
//    4 fully-unrolled LDS.128 iterations (hoisted-load block <= 64 regs,
//    half the LDS instruction count of R7)
//  - single rmin[8] tree-min (was lo/hi pairs)
// Keep RG=8 (prep amortization R12 lost), p and q staged in SMEM (SoA, p
// negated, half-norms). 8 warps = 4 row-blocks(256 rows) x 2 col-halves(512).
// Row mins: shfl tree -> SMEM atomicMin (merges the 2 col-half warps).
// Col mins: SMEM atomicMin at end (merges the 2 row-block... 4 row-block
// warps per half). Fused deterministic final reduction via done-ticket.
// Math: u = 0.5*d^2 via packed f32x2 FMA, norms folded into accumulator
// init, sqrt hoisted outside the mins. Fully deterministic.

#define NPTS    1024
#define THREADS 256
#define NWARPS  8
#define RG      8
#define CB_MAX  128

typedef unsigned long long ull;

#define PACK2(d, lo, hi) \
    asm("mov.b64 %0, {%1,%2};" : "=l"(d) : "f"(lo), "f"(hi))
#define UNPACK2(lo, hi, s) \
    asm("mov.b64 {%0,%1}, %2;" : "=f"(lo), "=f"(hi) : "l"(s))
#define FMA2(d, a, b, c) \
    asm("fma.rn.f32x2 %0, %1, %2, %3;" : "=l"(d) : "l"(a), "l"(b), "l"(c))
#define ADD2(d, a, b) \
    asm("add.rn.f32x2 %0, %1, %2;" : "=l"(d) : "l"(a), "l"(b))

__device__ float g_partials[CB_MAX];
__device__ int   g_done;   // zero-init; reset by last CTA each run

__global__ __launch_bounds__(THREADS, 1)
void chamfer_pair_kernel(const float* __restrict__ p, const float* __restrict__ q,
                         float* __restrict__ out, int cb_count) {
    __shared__ __align__(16) float qx_s[NPTS], qy_s[NPTS], qz_s[NPTS], qs_s[NPTS];
    __shared__ __align__(16) float px_s[NPTS], py_s[NPTS], pz_s[NPTS], ps_s[NPTS];
    __shared__ unsigned rowmin_sh[NPTS];
    __shared__ unsigned colmin_sh[NPTS];
    __shared__ float sred[NWARPS];
    __shared__ int sh_last;

    const int cb   = blockIdx.x;
    const int tid  = threadIdx.x;
    const int warp = tid >> 5;
    const int lane = tid & 31;
    const int rb = warp >> 1;          // row block 0..3 (256 rows)
    const int ch = warp & 1;           // column half 0..1 (512 cols)
    const float INF = __int_as_float(0x7f800000);

    const float4* __restrict__ qp = reinterpret_cast<const float4*>(q) + (size_t)cb * NPTS;
    const float4* __restrict__ pp = reinterpret_cast<const float4*>(p) + (size_t)cb * NPTS;

    // Stage both point sets (SoA, p negated, half-norms); init min buffers.
    for (int i = tid; i < NPTS; i += THREADS) {
        float4 v = qp[i];
        qx_s[i] = v.y; qy_s[i] = v.z; qz_s[i] = v.w;
        qs_s[i] = 0.5f * (v.y * v.y + v.z * v.z + v.w * v.w);
        float4 u = pp[i];
        px_s[i] = -u.y; py_s[i] = -u.z; pz_s[i] = -u.w;
        ps_s[i] = 0.5f * (u.y * u.y + u.z * u.z + u.w * u.w);
        rowmin_sh[i] = 0x7f800000u;
        colmin_sh[i] = 0x7f800000u;
    }
    __syncthreads();

    // Lane owns cols ch*512 + j4*128 + lane*4 + {0..3}, j4 = 0..3 -> colmin[16].
    float colmin[16];
    #pragma unroll
    for (int j = 0; j < 16; ++j) colmin[j] = INF;

    const int colbase0 = (ch << 9) + (lane << 2);

    #pragma unroll 1
    for (int rg = 0; rg < 32; ++rg) {              // 32 groups of 8 rows
        const int row0 = rb * 256 + rg * RG;
        ull pnx2[RG], pny2[RG], pnz2[RG], psq2[RG];
        float rmin[RG];
        #pragma unroll
        for (int r = 0; r < RG; ++r) {
            int row = row0 + r;
            float a = px_s[row], b = py_s[row];    // broadcast LDS
            float c = pz_s[row], s = ps_s[row];
            PACK2(pnx2[r], a, a);
            PACK2(pny2[r], b, b);
            PACK2(pnz2[r], c, c);
            PACK2(psq2[r], s, s);
            rmin[r] = INF;
        }
        #pragma unroll
        for (int j4 = 0; j4 < 4; ++j4) {           // 128 cols per j4; 512 total
            const int base = colbase0 + (j4 << 7); // 16B-aligned
            ulonglong2 xx = *reinterpret_cast<const ulonglong2*>(qx_s + base);
            ulonglong2 yy = *reinterpret_cast<const ulonglong2*>(qy_s + base);
            ulonglong2 zz = *reinterpret_cast<const ulonglong2*>(qz_s + base);
            ulonglong2 ss = *reinterpret_cast<const ulonglong2*>(qs_s + base);
            #pragma unroll
            for (int r = 0; r < RG; ++r) {
                ull a01, a23;
                ADD2(a01, ss.x, psq2[r]);          // 0.5|q|^2 + 0.5|p|^2
                ADD2(a23, ss.y, psq2[r]);
                FMA2(a01, pnx2[r], xx.x, a01);     // - px*qx
                FMA2(a23, pnx2[r], xx.y, a23);
                FMA2(a01, pny2[r], yy.x, a01);
                FMA2(a23, pny2[r], yy.y, a23);
                FMA2(a01, pnz2[r], zz.x, a01);     // = 0.5*d2, 4 columns
                FMA2(a23, pnz2[r], zz.y, a23);
                float u0, u1, u2, u3;
                UNPACK2(u0, u1, a01);
                UNPACK2(u2, u3, a23);
                colmin[4 * j4 + 0] = fminf(colmin[4 * j4 + 0], u0);
                colmin[4 * j4 + 1] = fminf(colmin[4 * j4 + 1], u1);
                colmin[4 * j4 + 2] = fminf(colmin[4 * j4 + 2], u2);
                colmin[4 * j4 + 3] = fminf(colmin[4 * j4 + 3], u3);
                rmin[r] = fminf(rmin[r], fminf(fminf(u0, u1), fminf(u2, u3)));
            }
        }
        // Row mins over this warp's 512 cols -> SMEM atomicMin (2 warps/row).
        #pragma unroll
        for (int r = 0; r < RG; ++r) {
            float m = rmin[r];
            #pragma unroll
            for (int off = 16; off > 0; off >>= 1)
                m = fminf(m, __shfl_xor_sync(0xffffffffu, m, off));
            if (lane == 0)
                atomicMin(&rowmin_sh[row0 + r], __float_as_uint(fmaxf(m, 0.0f)));
        }
    }

    // Column-min merge (4 row-block warps share each column half).
    #pragma unroll
    for (int j4 = 0; j4 < 4; ++j4) {
        #pragma unroll
        for (int k = 0; k < 4; ++k) {
            int c = colbase0 + (j4 << 7) + k;
            float v = fmaxf(colmin[4 * j4 + k], 0.0f);
            atomicMin(&colmin_sh[c], __float_as_uint(v));
        }
    }
    __syncthreads();

    // Per-thread partial: 4 rows + 4 cols each, fixed order.
    float acc = 0.0f;
    for (int i = tid; i < NPTS; i += THREADS) {
        acc += sqrtf(2.0f * __uint_as_float(rowmin_sh[i]) + 1e-12f);   // clamped
        acc += sqrtf(2.0f * __uint_as_float(colmin_sh[i]) + 1e-12f);   // clamped
    }
    #pragma unroll
    for (int off = 16; off > 0; off >>= 1)
        acc += __shfl_xor_sync(0xffffffffu, acc, off);
    if (lane == 0) sred[warp] = acc;
    __syncthreads();

    // Per-CTA total + done-ticket.
    if (tid == 0) {
        float total = 0.0f;
        #pragma unroll
        for (int w = 0; w < NWARPS; ++w) total += sred[w];
        g_partials[cb] = total;
        __threadfence();                       // partial visible before ticket
        int prev = atomicAdd(&g_done, 1);
        sh_last = (prev == cb_count - 1) ? 1 : 0;
    }
    __syncthreads();

    // Last CTA: deterministic fixed-order final reduction over all pairs.
    if (sh_last) {
        __threadfence();                       // observe all partials (L2)
        float v = (tid < cb_count) ? __ldcg(&g_partials[tid]) : 0.0f;
        #pragma unroll
        for (int off = 16; off > 0; off >>= 1)
            v += __shfl_xor_sync(0xffffffffu, v, off);
        if (lane == 0) sred[warp] = v;
        __syncthreads();
        if (tid == 0) {
            float tot = 0.0f;
            #pragma unroll
            for (int w = 0; w < NWARPS; ++w) tot += sred[w];
            out[0] = tot;
            g_done = 0;                        // reset for next graph replay
        }
    }
}

extern "C" void kernel_launch(void* const* d_in, const int* in_sizes, int n_in,
                              void* d_out, int out_size) {
    const float* p = (const float*)d_in[0];
    const float* q = (const float*)d_in[1];
    float* out = (float*)d_out;

    int cb = in_sizes[0] / (NPTS * 4);   // = 128 for (2,64,1024,4)
    if (cb > CB_MAX) cb = CB_MAX;

    chamfer_pair_kernel<<<cb, THREADS>>>(p, q, out, cb);
}

// round 15
// speedup vs baseline: 1.5923x; 1.2723x over previous
#include <cuda_runtime.h>
#include <cuda_bf16.h>

// ChamferLoss R14: register colmin + 4 warps/SMSP + provably-fitting regs.
// 512 threads, 16 warps = 4 row-blocks(256 rows) x 4 col-quarters(256 cols).
// Warp keeps colmin[8] in REGISTERS with only 2 fully-unrolled LDS.128
// column iterations (hoisted-load block = 32 regs). RG=8 packed-p = 64 regs.
// Demand ~127 <= 128-reg cap at 512 threads -> no spills, no ptxas
// double-buffer bloat, 4 warps/SMSP for latency hiding.
// Row mins: REDUX.MIN (__reduce_min_sync) on clamped bits (~4 slots/row,
// replaces the 11-slot shfl tree) -> SMEM atomicMin merges 4 col-quarter
// warps. Col mins: SMEM atomicMin at end merges 4 row-block warps.
// Math: u = 0.5*d^2 via packed f32x2 FMA, both half-norms folded into the
// accumulator init; sqrt hoisted outside the mins. Fused deterministic
// final reduction via done-ticket. One CTA per (c,b) pair.

#define NPTS    1024
#define THREADS 512
#define NWARPS  16
#define RG      8
#define CB_MAX  128

typedef unsigned long long ull;

#define PACK2(d, lo, hi) \
    asm("mov.b64 %0, {%1,%2};" : "=l"(d) : "f"(lo), "f"(hi))
#define UNPACK2(lo, hi, s) \
    asm("mov.b64 {%0,%1}, %2;" : "=f"(lo), "=f"(hi) : "l"(s))
#define FMA2(d, a, b, c) \
    asm("fma.rn.f32x2 %0, %1, %2, %3;" : "=l"(d) : "l"(a), "l"(b), "l"(c))
#define ADD2(d, a, b) \
    asm("add.rn.f32x2 %0, %1, %2;" : "=l"(d) : "l"(a), "l"(b))

__device__ float g_partials[CB_MAX];
__device__ int   g_done;   // zero-init; reset by last CTA each run

__global__ __launch_bounds__(THREADS, 1)
void chamfer_pair_kernel(const float* __restrict__ p, const float* __restrict__ q,
                         float* __restrict__ out, int cb_count) {
    __shared__ __align__(16) float qx_s[NPTS], qy_s[NPTS], qz_s[NPTS], qs_s[NPTS];
    __shared__ __align__(16) float px_s[NPTS], py_s[NPTS], pz_s[NPTS], ps_s[NPTS];
    __shared__ unsigned rowmin_sh[NPTS];
    __shared__ unsigned colmin_sh[NPTS];
    __shared__ float sred[NWARPS];
    __shared__ int sh_last;

    const int cb   = blockIdx.x;
    const int tid  = threadIdx.x;
    const int warp = tid >> 5;
    const int lane = tid & 31;
    const int rb = warp >> 2;          // row block 0..3   (256 rows)
    const int cq = warp & 3;           // column quarter 0..3 (256 cols)
    const float INF = __int_as_float(0x7f800000);

    const float4* __restrict__ qp = reinterpret_cast<const float4*>(q) + (size_t)cb * NPTS;
    const float4* __restrict__ pp = reinterpret_cast<const float4*>(p) + (size_t)cb * NPTS;

    // Stage both point sets (SoA, p negated, half-norms); init min buffers.
    for (int i = tid; i < NPTS; i += THREADS) {
        float4 v = qp[i];
        qx_s[i] = v.y; qy_s[i] = v.z; qz_s[i] = v.w;
        qs_s[i] = 0.5f * (v.y * v.y + v.z * v.z + v.w * v.w);
        float4 u = pp[i];
        px_s[i] = -u.y; py_s[i] = -u.z; pz_s[i] = -u.w;
        ps_s[i] = 0.5f * (u.y * u.y + u.z * u.z + u.w * u.w);
        rowmin_sh[i] = 0x7f800000u;
        colmin_sh[i] = 0x7f800000u;
    }
    __syncthreads();

    // Lane owns cols cq*256 + j4*128 + lane*4 + {0..3}, j4 = 0..1 -> colmin[8].
    float colmin[8];
    #pragma unroll
    for (int j = 0; j < 8; ++j) colmin[j] = INF;

    const int colbase0 = (cq << 8) + (lane << 2);

    #pragma unroll 1
    for (int rg = 0; rg < 32; ++rg) {              // 32 groups of 8 rows
        const int row0 = rb * 256 + rg * RG;
        ull pnx2[RG], pny2[RG], pnz2[RG], psq2[RG];
        float rmin[RG];
        #pragma unroll
        for (int r = 0; r < RG; ++r) {
            int row = row0 + r;
            float a = px_s[row], b = py_s[row];    // broadcast LDS
            float c = pz_s[row], s = ps_s[row];
            PACK2(pnx2[r], a, a);
            PACK2(pny2[r], b, b);
            PACK2(pnz2[r], c, c);
            PACK2(psq2[r], s, s);
            rmin[r] = INF;
        }
        #pragma unroll
        for (int j4 = 0; j4 < 2; ++j4) {           // 128 cols per j4; 256 total
            const int base = colbase0 + (j4 << 7); // 16B-aligned
            ulonglong2 xx = *reinterpret_cast<const ulonglong2*>(qx_s + base);
            ulonglong2 yy = *reinterpret_cast<const ulonglong2*>(qy_s + base);
            ulonglong2 zz = *reinterpret_cast<const ulonglong2*>(qz_s + base);
            ulonglong2 ss = *reinterpret_cast<const ulonglong2*>(qs_s + base);
            #pragma unroll
            for (int r = 0; r < RG; ++r) {
                ull a01, a23;
                ADD2(a01, ss.x, psq2[r]);          // 0.5|q|^2 + 0.5|p|^2
                ADD2(a23, ss.y, psq2[r]);
                FMA2(a01, pnx2[r], xx.x, a01);     // - px*qx
                FMA2(a23, pnx2[r], xx.y, a23);
                FMA2(a01, pny2[r], yy.x, a01);
                FMA2(a23, pny2[r], yy.y, a23);
                FMA2(a01, pnz2[r], zz.x, a01);     // = 0.5*d2, 4 columns
                FMA2(a23, pnz2[r], zz.y, a23);
                float u0, u1, u2, u3;
                UNPACK2(u0, u1, a01);
                UNPACK2(u2, u3, a23);
                colmin[4 * j4 + 0] = fminf(colmin[4 * j4 + 0], u0);
                colmin[4 * j4 + 1] = fminf(colmin[4 * j4 + 1], u1);
                colmin[4 * j4 + 2] = fminf(colmin[4 * j4 + 2], u2);
                colmin[4 * j4 + 3] = fminf(colmin[4 * j4 + 3], u3);
                rmin[r] = fminf(rmin[r], fminf(fminf(u0, u1), fminf(u2, u3)));
            }
        }
        // Row mins over this warp's 256 cols: REDUX.MIN on clamped bits.
        #pragma unroll
        for (int r = 0; r < RG; ++r) {
            unsigned mb = __float_as_uint(fmaxf(rmin[r], 0.0f));
            mb = __reduce_min_sync(0xffffffffu, mb);
            if (lane == 0)
                atomicMin(&rowmin_sh[row0 + r], mb);  // merge 4 col-quarter warps
        }
    }

    // Column-min merge (4 row-block warps share each column quarter).
    #pragma unroll
    for (int j4 = 0; j4 < 2; ++j4) {
        #pragma unroll
        for (int k = 0; k < 4; ++k) {
            int c = colbase0 + (j4 << 7) + k;
            float v = fmaxf(colmin[4 * j4 + k], 0.0f);
            atomicMin(&colmin_sh[c], __float_as_uint(v));
        }
    }
    __syncthreads();

    // Per-thread partial: 2 rows + 2 cols each, fixed order.
    float acc = 0.0f;
    for (int i = tid; i < NPTS; i += THREADS) {
        acc += sqrtf(2.0f * __uint_as_float(rowmin_sh[i]) + 1e-12f);   // clamped
        acc += sqrtf(2.0f * __uint_as_float(colmin_sh[i]) + 1e-12f);   // clamped
    }
    #pragma unroll
    for (int off = 16; off > 0; off >>= 1)
        acc += __shfl_xor_sync(0xffffffffu, acc, off);
    if (lane == 0) sred[warp] = acc;
    __syncthreads();

    // Per-CTA total + done-ticket.
    if (tid == 0) {
        float total = 0.0f;
        #pragma unroll
        for (int w = 0; w < NWARPS; ++w) total += sred[w];
        g_partials[cb] = total;
        __threadfence();                       // partial visible before ticket
        int prev = atomicAdd(&g_done, 1);
        sh_last = (prev == cb_count - 1) ? 1 : 0;
    }
    __syncthreads();

    // Last CTA: deterministic fixed-order final reduction over all pairs.
    if (sh_last) {
        __threadfence();                       // observe all partials (L2)
        float v = (tid < cb_count) ? __ldcg(&g_partials[tid]) : 0.0f;
        #pragma unroll
        for (int off = 16; off > 0; off >>= 1)
            v += __shfl_xor_sync(0xffffffffu, v, off);
        if (lane == 0) sred[warp] = v;
        __syncthreads();
        if (tid == 0) {
            float tot = 0.0f;
            #pragma unroll
            for (int w = 0; w < NWARPS; ++w) tot += sred[w];
            out[0] = tot;
            g_done = 0;                        // reset for next graph replay
        }
    }
}

extern "C" void kernel_launch(void* const* d_in, const int* in_sizes, int n_in,
                              void* d_out, int out_size) {
    const float* p = (const float*)d_in[0];
    const float* q = (const float*)d_in[1];
    float* out = (float*)d_out;

    int cb = in_sizes[0] / (NPTS * 4);   // = 128 for (2,64,1024,4)
    if (cb > CB_MAX) cb = CB_MAX;

    chamfer_pair_kernel<<<cb, THREADS>>>(p, q, out, cb);
}